// round 15
// baseline (speedup 1.0000x reference)
#include <cuda_runtime.h>
#include <cooperative_groups.h>
#include <cstdint>

namespace cg = cooperative_groups;
using u64 = unsigned long long;
using u32 = unsigned int;

// Problem constants
constexpr int B = 32;
constexpr int N = 131072;
constexpr int K = 1024;

// Config
constexpr int C     = 4;        // CTAs per batch (cluster)
constexpr int T     = 1024;     // threads per CTA (32 warps)
constexpr int W     = T / 32;   // warps per CTA
constexpr int S     = N / C;    // 32768 pts per CTA slice
constexpr int CH    = 128;      // points per chunk
constexpr int NCH   = S / CH;   // 256 chunks per CTA
constexpr int CELLS = 4096;     // 16^3 Morton cells per batch

// Static device scratch (allocation-free): sorted SoA
__device__ __align__(16) float g_x[B * N];
__device__ __align__(16) float g_y[B * N];
__device__ __align__(16) float g_z[B * N];
__device__ __align__(16) int   g_i[B * N];   // original within-batch index

// ---- Morton cell id (4 bits/dim) ----
__device__ __forceinline__ u32 expand3_4(u32 v) {
    return (v & 1u) | ((v & 2u) << 2) | ((v & 4u) << 4) | ((v & 8u) << 6);
}
__device__ __forceinline__ int cell_of(float x, float y, float z) {
    int ix = min(15, max(0, (int)((x + 4.5f) * (16.0f / 9.0f))));
    int iy = min(15, max(0, (int)((y + 4.5f) * (16.0f / 9.0f))));
    int iz = min(15, max(0, (int)((z + 4.5f) * (16.0f / 9.0f))));
    return (int)(expand3_4((u32)ix) | (expand3_4((u32)iy) << 1) |
                 (expand3_4((u32)iz) << 2));
}

struct __align__(32) Slot {
    u32 lo, hi;        // packed best: (dist_bits<<32) | ~origidx
    float x, y, z;
    float pad0, pad1, pad2;
};

// SMEM layout (bytes) — dist region doubles as sort scratch in the prologue
constexpr int SM_DIST = 0;                         // S floats  = 131072
constexpr int SM_BOX  = SM_DIST + S * 4;           // NCH*6 f   =   6144
constexpr int SM_CB   = SM_BOX + NCH * 24;         // NCH u64   =   2048
constexpr int SM_CX   = SM_CB + NCH * 8;           // NCH f
constexpr int SM_CY   = SM_CX + NCH * 4;
constexpr int SM_CZ   = SM_CY + NCH * 4;
constexpr int SM_WL   = SM_CZ + NCH * 4;           // NCH u32 worklist
constexpr int SM_TF   = SM_WL + NCH * 4;           // NCH u32 touched flags
constexpr int SM_WC   = SM_TF + NCH * 4;           // 2 u32 + pad
constexpr int SM_BT   = SM_WC + 16;                // 2 u64 touched-best (parity)
constexpr int SM_UT   = SM_BT + 16;                // u64 key + u32 chunk + pad
constexpr int SM_SL   = SM_UT + 16;                // Slot[2][C]
constexpr int SMEM_TOTAL = SM_SL + 2 * C * 32;     // ~144.9 KB

__global__ void __cluster_dims__(C, 1, 1) __launch_bounds__(T, 1)
fps_kernel(const float* __restrict__ pts, const int* __restrict__ init_idx,
           float* __restrict__ out)
{
    extern __shared__ char smem[];
    float4* sd4  = (float4*)(smem + SM_DIST);
    float*  sbox = (float*)(smem + SM_BOX);
    u64*    scb  = (u64*)(smem + SM_CB);
    float*  scx  = (float*)(smem + SM_CX);
    float*  scy  = (float*)(smem + SM_CY);
    float*  scz  = (float*)(smem + SM_CZ);
    u32*    swl  = (u32*)(smem + SM_WL);
    u32*    stf  = (u32*)(smem + SM_TF);
    u32*    swc  = (u32*)(smem + SM_WC);
    u64*    sBT  = (u64*)(smem + SM_BT);
    u64*    sUTk = (u64*)(smem + SM_UT);
    u32*    sUTc = (u32*)(smem + SM_UT + 8);
    Slot*   sl   = (Slot*)(smem + SM_SL);

    // sort scratch overlays the dist region (freed before dist init)
    u32* PH = (u32*)(smem + SM_DIST);        // local hist   [CELLS]
    u32* PC = PH + CELLS;                    // cur/base     [CELLS]
    int* PW = (int*)(PC + CELLS);            // warp totals  [32]

    cg::cluster_group cluster = cg::this_cluster();
    const int rank = blockIdx.x;
    const int b    = blockIdx.y;
    const int t    = threadIdx.x;
    const int warp = t >> 5, lane = t & 31;
    const int bOff  = b * N;
    const int gbase = bOff + rank * S;

    // ======================= in-kernel preprocessing =======================
    #pragma unroll
    for (int j = 0; j < CELLS / T; j++) PH[t + j * T] = 0;
    __syncthreads();
    for (int i = t; i < S; i += T) {
        int gi = gbase + i;
        float x = pts[3 * gi], y = pts[3 * gi + 1], z = pts[3 * gi + 2];
        atomicAdd(&PH[cell_of(x, y, z)], 1u);
    }
    __syncthreads();
    cluster.sync();   // peers' hists complete

    {   // combine peer hists (DSMEM) + exclusive scan -> per-CTA base counters
        int v[4], mb[4];
        #pragma unroll
        for (int j = 0; j < 4; j++) {
            int cell = t * 4 + j;
            int tot = 0, base = 0;
            #pragma unroll
            for (int r = 0; r < C; r++) {
                u32* hp = (u32*)cluster.map_shared_rank(PH + cell, r);
                int h = (int)*hp;
                if (r < rank) base += h;
                tot += h;
            }
            v[j] = tot; mb[j] = base;
        }
        int s = v[0] + v[1] + v[2] + v[3];
        int ps = s;
        #pragma unroll
        for (int o = 1; o < 32; o <<= 1) {
            int u = __shfl_up_sync(0xffffffffu, ps, o);
            if (lane >= o) ps += u;
        }
        if (lane == 31) PW[warp] = ps;
        __syncthreads();
        if (warp == 0) {
            int x = PW[lane];
            #pragma unroll
            for (int o = 1; o < 32; o <<= 1) {
                int u = __shfl_up_sync(0xffffffffu, x, o);
                if (lane >= o) x += u;
            }
            PW[lane] = x;
        }
        __syncthreads();
        int run = (warp > 0 ? PW[warp - 1] : 0) + (ps - s);
        #pragma unroll
        for (int j = 0; j < 4; j++) {
            PC[t * 4 + j] = (u32)(run + mb[j]);
            run += v[j];
        }
    }
    __syncthreads();

    for (int i = t; i < S; i += T) {     // scatter into batch-sorted SoA
        int gi = gbase + i;
        float x = pts[3 * gi], y = pts[3 * gi + 1], z = pts[3 * gi + 2];
        int cell = cell_of(x, y, z);
        int pos = (int)atomicAdd(&PC[cell], 1u);
        int o = bOff + pos;
        g_x[o] = x; g_y[o] = y; g_z[o] = z; g_i[o] = gi - bOff;
    }
    __threadfence();
    __syncthreads();
    cluster.sync();   // all batch points sorted & visible

    const float4* __restrict__ gx4 = (const float4*)(g_x + gbase);
    const float4* __restrict__ gy4 = (const float4*)(g_y + gbase);
    const float4* __restrict__ gz4 = (const float4*)(g_z + gbase);
    const int4*   __restrict__ gi4 = (const int4*)(g_i + gbase);

    // per-chunk bboxes into SMEM (one warp per chunk)
    for (int c = warp; c < NCH; c += W) {
        int f = c * 32 + lane;
        float4 X = gx4[f], Y = gy4[f], Z = gz4[f];
        float mnx = fminf(fminf(X.x, X.y), fminf(X.z, X.w));
        float mxx = fmaxf(fmaxf(X.x, X.y), fmaxf(X.z, X.w));
        float mny = fminf(fminf(Y.x, Y.y), fminf(Y.z, Y.w));
        float mxy = fmaxf(fmaxf(Y.x, Y.y), fmaxf(Y.z, Y.w));
        float mnz = fminf(fminf(Z.x, Z.y), fminf(Z.z, Z.w));
        float mxz = fmaxf(fmaxf(Z.x, Z.y), fmaxf(Z.z, Z.w));
        #pragma unroll
        for (int s2 = 16; s2 > 0; s2 >>= 1) {
            mnx = fminf(mnx, __shfl_xor_sync(0xffffffffu, mnx, s2));
            mxx = fmaxf(mxx, __shfl_xor_sync(0xffffffffu, mxx, s2));
            mny = fminf(mny, __shfl_xor_sync(0xffffffffu, mny, s2));
            mxy = fmaxf(mxy, __shfl_xor_sync(0xffffffffu, mxy, s2));
            mnz = fminf(mnz, __shfl_xor_sync(0xffffffffu, mnz, s2));
            mxz = fmaxf(mxz, __shfl_xor_sync(0xffffffffu, mxz, s2));
        }
        if (lane == 0) {
            float* bb = &sbox[c * 6];
            bb[0] = mnx; bb[1] = mxx; bb[2] = mny;
            bb[3] = mxy; bb[4] = mnz; bb[5] = mxz;
        }
    }
    __syncthreads();

    // dist init (overwrites sort scratch) + chunk state + first point
    #pragma unroll
    for (int j = 0; j < S / (4 * T); j++)
        sd4[t + j * T] = make_float4(1e10f, 1e10f, 1e10f, 1e10f);
    if (t < NCH) {
        scb[t] = ((u64)__float_as_uint(1e10f)) << 32;   // forces touch at k=1
        scx[t] = 0.f; scy[t] = 0.f; scz[t] = 0.f;
    }
    if (t == 0) { swc[0] = 0; swc[1] = 0; sBT[0] = 0ULL; sBT[1] = 0ULL; }

    const int idx0 = init_idx[b];
    float lx = pts[3 * (bOff + idx0) + 0];
    float ly = pts[3 * (bOff + idx0) + 1];
    float lz = pts[3 * (bOff + idx0) + 2];
    if (rank == 0 && t == 0) {
        out[(b * K + 0) * 3 + 0] = lx;
        out[(b * K + 0) * 3 + 1] = ly;
        out[(b * K + 0) * 3 + 2] = lz;
    }
    __syncthreads();

    // ======================= K-1 sequential iterations ======================
    for (int k = 1; k < K; k++) {
        const int ph = k & 1;

        // phase A: reset next-parity state; bound-check all chunks, flag+worklist
        if (t == 0) { swc[ph ^ 1] = 0; sBT[ph ^ 1] = 0ULL; }
        if (t < NCH) {
            const float* bb = &sbox[t * 6];
            float dx = fmaxf(0.0f, fmaxf(bb[0] - lx, lx - bb[1]));
            float dy = fmaxf(0.0f, fmaxf(bb[2] - ly, ly - bb[3]));
            float dz = fmaxf(0.0f, fmaxf(bb[4] - lz, lz - bb[5]));
            float lb2 = __fmaf_rn(dx, dx, __fmaf_rn(dy, dy, dz * dz));
            float cub = __uint_as_float((u32)(scb[t] >> 32));
            bool touched = (lb2 * 0.99999f < cub);  // conservative margin
            stf[t] = touched ? 1u : 0u;
            if (touched) {
                u32 p = atomicAdd(&swc[ph], 1u);
                swl[p] = (u32)t;
            }
        }
        __syncthreads();
        const int nw = (int)swc[ph];

        // warp best across all chunks this warp processes (phase B warps)
        u64 wbK = 0ULL; float wbX = 0.f, wbY = 0.f, wbZ = 0.f;

        if (warp == 0) {
            // overlapped with phase B: max over UNTOUCHED chunks (keys final)
            u64 bk = 0ULL; int bc = 0;
            #pragma unroll
            for (int i = 0; i < NCH / 32; i++) {
                int c = lane + 32 * i;
                if (!stf[c]) {
                    u64 e = scb[c];
                    if (e > bk) { bk = e; bc = c; }
                }
            }
            #pragma unroll
            for (int o = 16; o > 0; o >>= 1) {
                u64 ok = __shfl_xor_sync(0xffffffffu, bk, o);
                int oc = __shfl_xor_sync(0xffffffffu, bc, o);
                if (ok > bk) { bk = ok; bc = oc; }
            }
            if (lane == 0) { *sUTk = bk; *sUTc = (u32)bc; }
        } else {
            // phase B: warps 1..31, one warp per touched chunk
            for (int wi = warp - 1; wi < nw; wi += W - 1) {
                int c = (int)swl[wi];
                int f = c * 32 + lane;
                float4 X = gx4[f];
                float4 Y = gy4[f];
                float4 Z = gz4[f];
                int4   I = gi4[f];
                float4 D = sd4[f];
                const float* Xv = (const float*)&X;
                const float* Yv = (const float*)&Y;
                const float* Zv = (const float*)&Z;
                const int*   Iv = (const int*)&I;
                float* Dv = (float*)&D;
                u64 bk = 0ULL;
                float bx = 0.f, by = 0.f, bz = 0.f;
                #pragma unroll
                for (int cc = 0; cc < 4; cc++) {
                    float dx = Xv[cc] - lx, dy = Yv[cc] - ly, dz = Zv[cc] - lz;
                    float d2 = __fmaf_rn(dx, dx, __fmaf_rn(dy, dy, dz * dz));
                    float nd = fminf(Dv[cc], d2);
                    Dv[cc] = nd;
                    u64 key = (((u64)__float_as_uint(nd)) << 32) |
                              (u32)(~(u32)Iv[cc]);
                    if (key > bk) { bk = key; bx = Xv[cc]; by = Yv[cc]; bz = Zv[cc]; }
                }
                sd4[f] = D;
                #pragma unroll
                for (int o = 16; o > 0; o >>= 1) {
                    u64   ok = __shfl_xor_sync(0xffffffffu, bk, o);
                    float ox = __shfl_xor_sync(0xffffffffu, bx, o);
                    float oy = __shfl_xor_sync(0xffffffffu, by, o);
                    float oz = __shfl_xor_sync(0xffffffffu, bz, o);
                    if (ok > bk) { bk = ok; bx = ox; by = oy; bz = oz; }
                }
                if (lane == 0) {
                    scb[c] = bk;
                    scx[c] = bx; scy[c] = by; scz[c] = bz;
                }
                if (bk > wbK) { wbK = bk; wbX = bx; wbY = by; wbZ = bz; }
            }
            if (lane == 0 && wbK != 0ULL) atomicMax(&sBT[ph], wbK);
        }
        __syncthreads();

        // owner election + push (O(1), no serial rescan)
        const u64 tb = sBT[ph];
        const u64 ub = *sUTk;
        if (lane == 0) {
            bool iPush = false;
            u64 key = 0ULL; float px = 0.f, py = 0.f, pz = 0.f;
            if (warp == 0) {
                if (ub >= tb) {            // untouched chunk wins (keys unique)
                    iPush = true; key = ub;
                    int uc = (int)*sUTc;
                    px = scx[uc]; py = scy[uc]; pz = scz[uc];
                }
            } else if (tb > ub && wbK == tb) {  // exactly one touched warp matches
                iPush = true; key = tb;
                px = wbX; py = wbY; pz = wbZ;
            }
            if (iPush) {
                Slot* my = &sl[ph * C + rank];
                uint4 w = make_uint4((u32)(key & 0xffffffffull),
                                     (u32)(key >> 32),
                                     __float_as_uint(px),
                                     __float_as_uint(py));
                #pragma unroll
                for (int r = 0; r < C; r++) {
                    Slot* p = (Slot*)cluster.map_shared_rank(my, r);
                    *(uint4*)p = w;
                    p->z = pz;
                }
            }
        }

        cluster.sync();   // HW-sleep barrier; orders remote slot stores

        // every thread picks the cluster winner from local slots (coords incl.)
        u64 gb = 0ULL;
        float nx = 0.f, ny = 0.f, nz = 0.f;
        #pragma unroll
        for (int r = 0; r < C; r++) {
            const Slot* p = &sl[ph * C + r];
            uint4 w = *(const uint4*)p;
            float z = p->z;
            u64 v = ((u64)w.y << 32) | w.x;
            if (v > gb) {
                gb = v;
                nx = __uint_as_float(w.z);
                ny = __uint_as_float(w.w);
                nz = z;
            }
        }
        lx = nx; ly = ny; lz = nz;

        if (rank == 0 && t == 0) {
            out[(b * K + k) * 3 + 0] = lx;
            out[(b * K + k) * 3 + 1] = ly;
            out[(b * K + k) * 3 + 2] = lz;
        }
    }

    cluster.sync();   // keep SMEM alive until all peer traffic retired
}

extern "C" void kernel_launch(void* const* d_in, const int* in_sizes, int n_in,
                              void* d_out, int out_size) {
    const float* pts  = (const float*)d_in[0];
    const int*   init = (const int*)d_in[1];
    float*       out  = (float*)d_out;

    cudaFuncSetAttribute(fps_kernel,
                         cudaFuncAttributeMaxDynamicSharedMemorySize, SMEM_TOTAL);

    dim3 grid(C, B, 1);
    fps_kernel<<<grid, T, SMEM_TOTAL>>>(pts, init, out);
}